// round 4
// baseline (speedup 1.0000x reference)
#include <cuda_runtime.h>
#include <cuda_bf16.h>

#define N_NODES 50000
#define N_EDGES 800000
#define D 128

typedef unsigned long long u64;

// ---------------------------------------------------------------------------
// Scratch (__device__ globals per allocation-free rule)
// ---------------------------------------------------------------------------
__device__ __align__(16) float g_agg[N_NODES * D];   // normalized mean agg
__device__ int g_cnt[N_NODES];        // in-degree (histogram)
__device__ int g_off[N_NODES];        // CSR row offsets (exclusive prefix)
__device__ int g_cur[N_NODES];        // fill cursors
__device__ int g_csr[N_EDGES];        // src node per CSR slot

// ---------------------------------------------------------------------------
// K1: zero the degree histogram
// ---------------------------------------------------------------------------
__global__ void zero_cnt() {
    int i = blockIdx.x * blockDim.x + threadIdx.x;
    if (i < N_NODES) g_cnt[i] = 0;
}

// ---------------------------------------------------------------------------
// K2: degree histogram over destinations
// ---------------------------------------------------------------------------
__global__ void __launch_bounds__(256) hist_kernel(const int* __restrict__ ei) {
    int e = blockIdx.x * blockDim.x + threadIdx.x;
    if (e >= N_EDGES) return;
    int dst = ei[N_EDGES + e];
    if ((unsigned)dst < N_NODES) atomicAdd(&g_cnt[dst], 1);
}

// ---------------------------------------------------------------------------
// K3: single-block exclusive scan -> g_off, g_cur
// ---------------------------------------------------------------------------
__global__ void __launch_bounds__(1024) scan_kernel() {
    __shared__ int part[1024];
    const int t = threadIdx.x;
    const int CH = (N_NODES + 1023) / 1024;      // 49
    int beg = t * CH;
    int end = beg + CH; if (end > N_NODES) end = N_NODES;
    int s = 0;
    #pragma unroll 7
    for (int i = beg; i < end; i++) s += g_cnt[i];
    part[t] = s;
    __syncthreads();
    #pragma unroll
    for (int off = 1; off < 1024; off <<= 1) {
        int tmp = 0;
        if (t >= off) tmp = part[t - off];
        __syncthreads();
        if (t >= off) part[t] += tmp;
        __syncthreads();
    }
    int run = part[t] - s;
    for (int i = beg; i < end; i++) {
        g_off[i] = run;
        g_cur[i] = run;
        run += g_cnt[i];
    }
}

// ---------------------------------------------------------------------------
// K4: bucket fill — scatter src ids into CSR slots
// ---------------------------------------------------------------------------
__global__ void __launch_bounds__(256) fill_kernel(const int* __restrict__ ei) {
    int e = blockIdx.x * blockDim.x + threadIdx.x;
    if (e >= N_EDGES) return;
    int src = ei[e];
    int dst = ei[N_EDGES + e];
    if ((unsigned)src >= N_NODES || (unsigned)dst >= N_NODES) return;
    int pos = atomicAdd(&g_cur[dst], 1);
    g_csr[pos] = src;
}

// ---------------------------------------------------------------------------
// K5: gather-aggregate. One warp per node; lane owns float4 of the row.
// Chunked: lanes coalesced-load 32 CSR indices, shfl-broadcast, then issue
// up to 32 INDEPENDENT row loads (deep MLP, no loop-carried load chain).
// ---------------------------------------------------------------------------
__global__ void __launch_bounds__(256) gather_kernel(const float* __restrict__ x) {
    unsigned tid = blockIdx.x * blockDim.x + threadIdx.x;
    unsigned n = tid >> 5;
    unsigned lane = tid & 31;
    if (n >= N_NODES) return;

    const int beg = g_off[n];
    const int deg = g_cnt[n];

    float4 acc = make_float4(0.f, 0.f, 0.f, 0.f);

    for (int base = 0; base < deg; base += 32) {
        int rem = deg - base;
        int m = rem < 32 ? rem : 32;
        int idx = 0;
        if ((int)lane < m) idx = g_csr[beg + base + lane];

        int j = 0;
        // unrolled-by-4 body: 4 independent loads in flight per step
        for (; j + 4 <= m; j += 4) {
            int s0 = __shfl_sync(0xffffffffu, idx, j + 0);
            int s1 = __shfl_sync(0xffffffffu, idx, j + 1);
            int s2 = __shfl_sync(0xffffffffu, idx, j + 2);
            int s3 = __shfl_sync(0xffffffffu, idx, j + 3);
            float4 v0 = *(const float4*)(x + (size_t)s0 * D + lane * 4);
            float4 v1 = *(const float4*)(x + (size_t)s1 * D + lane * 4);
            float4 v2 = *(const float4*)(x + (size_t)s2 * D + lane * 4);
            float4 v3 = *(const float4*)(x + (size_t)s3 * D + lane * 4);
            acc.x += v0.x + v1.x + v2.x + v3.x;
            acc.y += v0.y + v1.y + v2.y + v3.y;
            acc.z += v0.z + v1.z + v2.z + v3.z;
            acc.w += v0.w + v1.w + v2.w + v3.w;
        }
        for (; j < m; j++) {
            int s0 = __shfl_sync(0xffffffffu, idx, j);
            float4 v = *(const float4*)(x + (size_t)s0 * D + lane * 4);
            acc.x += v.x; acc.y += v.y; acc.z += v.z; acc.w += v.w;
        }
    }

    float inv = 1.0f / fmaxf((float)deg, 1.0f);
    acc.x *= inv; acc.y *= inv; acc.z *= inv; acc.w *= inv;
    *(float4*)(g_agg + (size_t)n * D + lane * 4) = acc;
}

// ---------------------------------------------------------------------------
// K6: fused  out = relu( agg @ W_l^T + b_l + x @ W_r^T )
// Persistent CTAs (grid = 148): weights loaded ONCE per SM.
// Tile = 128 nodes x 128 cols; K=256 split into two 128-k phases
// (phase 0 streams agg, phase 1 streams x). Thread tile = 8 nodes x 8 cols,
// packed f32x2 FMA.
// ---------------------------------------------------------------------------
#define TN 128
#define WSTR 132
#define GEMM_GRID 148
#define N_TILES ((N_NODES + TN - 1) / TN)     // 391
#define SMEM_FLOATS (256 * WSTR + TN * D)
#define SMEM_BYTES  (SMEM_FLOATS * 4)         // 200,704 B

__device__ __forceinline__ void ffma2(u64& d, u64 a, u64 b) {
    asm("fma.rn.f32x2 %0, %1, %2, %0;" : "+l"(d) : "l"(a), "l"(b));
}

__global__ void __launch_bounds__(256, 1) sage_gemm(
    const float* __restrict__ x,
    const float* __restrict__ W_l,
    const float* __restrict__ b_l,
    const float* __restrict__ W_r,
    float* __restrict__ out)
{
    extern __shared__ float sm[];
    float* Wsm  = sm;                 // [256][WSTR]: Wsm[k][c] = Wcat[c][k]
    float* insm = sm + 256 * WSTR;    // [TN][128] node-major tile

    const int t = threadIdx.x;

    // Load both weights transposed (once per block)
    #pragma unroll 4
    for (int l = t; l < D * D; l += 256) {
        int c = l >> 7;
        int k = l & 127;
        Wsm[k * WSTR + c]         = W_l[l];
        Wsm[(k + 128) * WSTR + c] = W_r[l];
    }
    __syncthreads();

    const int c0 = (t & 15) * 8;     // 8 output cols
    const int n0 = (t >> 4) * 8;     // 8 nodes
    const float4 bias0 = *(const float4*)&b_l[c0];
    const float4 bias1 = *(const float4*)&b_l[c0 + 4];

    for (int tile = blockIdx.x; tile < N_TILES; tile += GEMM_GRID) {
        const int nodeBase = tile * TN;

        u64 acc[8][4];
        #pragma unroll
        for (int i = 0; i < 8; i++)
            #pragma unroll
            for (int j = 0; j < 4; j++) acc[i][j] = 0ull;

        #pragma unroll
        for (int phase = 0; phase < 2; phase++) {
            const float* srcmat = phase ? x : g_agg;

            // Fill input tile: 128x128 floats = 4096 float4, 16 per thread
            #pragma unroll 4
            for (int f = t; f < TN * D / 4; f += 256) {
                int node = f >> 5;          // 32 float4 per row
                int kq   = f & 31;
                int gn = nodeBase + node;
                float4 v = make_float4(0.f, 0.f, 0.f, 0.f);
                if (gn < N_NODES)
                    v = *(const float4*)(srcmat + (size_t)gn * D + kq * 4);
                *(float4*)&insm[node * D + kq * 4] = v;
            }
            __syncthreads();

            const float* wbase = Wsm + phase * 128 * WSTR;
            #pragma unroll 2
            for (int k = 0; k < 128; k++) {
                float4 wa = *(const float4*)&wbase[k * WSTR + c0];
                float4 wb = *(const float4*)&wbase[k * WSTR + c0 + 4];
                u64 w0, w1, w2, w3;
                asm("mov.b64 %0, {%1, %2};" : "=l"(w0) : "f"(wa.x), "f"(wa.y));
                asm("mov.b64 %0, {%1, %2};" : "=l"(w1) : "f"(wa.z), "f"(wa.w));
                asm("mov.b64 %0, {%1, %2};" : "=l"(w2) : "f"(wb.x), "f"(wb.y));
                asm("mov.b64 %0, {%1, %2};" : "=l"(w3) : "f"(wb.z), "f"(wb.w));
                #pragma unroll
                for (int i = 0; i < 8; i++) {
                    float a = insm[(n0 + i) * D + k];
                    u64 aa;
                    asm("mov.b64 %0, {%1, %1};" : "=l"(aa) : "f"(a));
                    ffma2(acc[i][0], aa, w0);
                    ffma2(acc[i][1], aa, w1);
                    ffma2(acc[i][2], aa, w2);
                    ffma2(acc[i][3], aa, w3);
                }
            }
            __syncthreads();
        }

        // Epilogue: bias + relu + store
        #pragma unroll
        for (int i = 0; i < 8; i++) {
            int gn = nodeBase + n0 + i;
            if (gn < N_NODES) {
                float r0, r1, r2, r3, r4, r5, r6, r7;
                asm("mov.b64 {%0, %1}, %2;" : "=f"(r0), "=f"(r1) : "l"(acc[i][0]));
                asm("mov.b64 {%0, %1}, %2;" : "=f"(r2), "=f"(r3) : "l"(acc[i][1]));
                asm("mov.b64 {%0, %1}, %2;" : "=f"(r4), "=f"(r5) : "l"(acc[i][2]));
                asm("mov.b64 {%0, %1}, %2;" : "=f"(r6), "=f"(r7) : "l"(acc[i][3]));
                float4 o0, o1;
                o0.x = fmaxf(r0 + bias0.x, 0.f);
                o0.y = fmaxf(r1 + bias0.y, 0.f);
                o0.z = fmaxf(r2 + bias0.z, 0.f);
                o0.w = fmaxf(r3 + bias0.w, 0.f);
                o1.x = fmaxf(r4 + bias1.x, 0.f);
                o1.y = fmaxf(r5 + bias1.y, 0.f);
                o1.z = fmaxf(r6 + bias1.z, 0.f);
                o1.w = fmaxf(r7 + bias1.w, 0.f);
                *(float4*)&out[(size_t)gn * D + c0]     = o0;
                *(float4*)&out[(size_t)gn * D + c0 + 4] = o1;
            }
        }
    }
}

// ---------------------------------------------------------------------------
extern "C" void kernel_launch(void* const* d_in, const int* in_sizes, int n_in,
                              void* d_out, int out_size) {
    const float* x   = (const float*)d_in[0];
    const int*   ei  = (const int*)d_in[1];
    const float* W_l = (const float*)d_in[2];
    const float* b_l = (const float*)d_in[3];
    const float* W_r = (const float*)d_in[4];
    float*       out = (float*)d_out;

    cudaFuncSetAttribute(sage_gemm,
                         cudaFuncAttributeMaxDynamicSharedMemorySize,
                         SMEM_BYTES);

    zero_cnt<<<(N_NODES + 255) / 256, 256>>>();
    hist_kernel<<<(N_EDGES + 255) / 256, 256>>>(ei);
    scan_kernel<<<1, 1024>>>();
    fill_kernel<<<(N_EDGES + 255) / 256, 256>>>(ei);
    gather_kernel<<<(N_NODES * 32 + 255) / 256, 256>>>(x);
    sage_gemm<<<GEMM_GRID, 256, SMEM_BYTES>>>(x, W_l, b_l, W_r, out);
}

// round 6
// speedup vs baseline: 1.9189x; 1.9189x over previous
#include <cuda_runtime.h>
#include <cuda_bf16.h>

#define N_NODES 50000
#define N_EDGES 800000
#define D 128

typedef unsigned long long u64;

// ---------------------------------------------------------------------------
// Scratch (__device__ globals per allocation-free rule)
// ---------------------------------------------------------------------------
__device__ __align__(16) float g_agg[N_NODES * D];   // 25.6 MB
__device__ __align__(16) float g_deg[N_NODES];

// ---------------------------------------------------------------------------
// K1: zero accumulation scratch
// ---------------------------------------------------------------------------
__global__ void zero_kernel() {
    int i = blockIdx.x * blockDim.x + threadIdx.x;
    const int n4 = (N_NODES * D) / 4;
    if (i < n4) ((float4*)g_agg)[i] = make_float4(0.f, 0.f, 0.f, 0.f);
    if (i < N_NODES) g_deg[i] = 0.f;
}

// ---------------------------------------------------------------------------
// K2: edge scatter, one warp per edge, vector L2 reductions
// ---------------------------------------------------------------------------
__device__ __forceinline__ void red_add_v4(float* addr, float4 v) {
    asm volatile("red.global.add.v4.f32 [%0], {%1, %2, %3, %4};"
                 :: "l"(addr), "f"(v.x), "f"(v.y), "f"(v.z), "f"(v.w)
                 : "memory");
}

__global__ void __launch_bounds__(256) scatter_kernel(
    const float* __restrict__ x,
    const int* __restrict__ ei)
{
    unsigned tid = blockIdx.x * blockDim.x + threadIdx.x;
    unsigned e = tid >> 5;
    unsigned lane = tid & 31;
    if (e >= N_EDGES) return;

    int src = ei[e];
    int dst = ei[N_EDGES + e];
    if ((unsigned)src >= N_NODES || (unsigned)dst >= N_NODES) return;

    float4 v = *(const float4*)(x + (size_t)src * D + lane * 4);
    red_add_v4(g_agg + (size_t)dst * D + lane * 4, v);

    if (lane == 0) atomicAdd(&g_deg[dst], 1.0f);
}

// ---------------------------------------------------------------------------
// K3: fused  out = relu( (agg/deg) @ W_l^T + b_l + x @ W_r^T )
//
// TN=64 nodes x 128 cols per 256-thread block. K = 256 (agg k:0..127, x
// k:128..255). Input tile stored TRANSPOSED (k-major, tileT[k][node],
// stride 64): adjacent nodes adjacent in smem, so ld.shared.v2.b64 yields
// node-PAIR operands for packed fma.rn.f32x2 with no duplication movs on
// the streamed operand. Inner loop: 23 issues per 64 MACs.
// ---------------------------------------------------------------------------
#define TN 64
#define WSTR 132
// float offsets in dynamic smem
#define OFF_W    0
#define OFF_T    (256 * WSTR)             // 33792
#define OFF_S    (OFF_T + 256 * TN)       // 50176
#define SMEM_FLOATS (OFF_S + TN)
#define SMEM_BYTES  (SMEM_FLOATS * 4)     // 200,960 B

__device__ __forceinline__ void ffma2(u64& d, u64 a, u64 b) {
    asm("fma.rn.f32x2 %0, %1, %2, %0;" : "+l"(d) : "l"(a), "l"(b));
}

__global__ void __launch_bounds__(256, 1) sage_gemm(
    const float* __restrict__ x,
    const float* __restrict__ W_l,
    const float* __restrict__ b_l,
    const float* __restrict__ W_r,
    float* __restrict__ out)
{
    extern __shared__ float sm[];
    float* Wsm   = sm + OFF_W;   // [256][WSTR]: Wsm[k][c] = Wcat[c][k]
    float* tileT = sm + OFF_T;   // [256][64] k-major
    float* ssm   = sm + OFF_S;   // [64] inv-deg

    const int t = threadIdx.x;
    const int nodeBase = blockIdx.x * TN;

    // Weights transposed into smem
    #pragma unroll 4
    for (int l = t; l < D * D; l += 256) {
        int c = l >> 7;
        int k = l & 127;
        Wsm[k * WSTR + c]         = W_l[l];
        Wsm[(k + 128) * WSTR + c] = W_r[l];
    }

    if (t < TN) {
        int n = nodeBase + t;
        float dg = (n < N_NODES) ? g_deg[n] : 1.0f;
        ssm[t] = 1.0f / fmaxf(dg, 1.0f);
    }
    __syncthreads();

    // Fill transposed tile. Warp spans 32 consecutive nodes at fixed kq:
    // STS addresses hit all 32 banks (conflict-free); LDG is 2x-sector
    // amplified (16B of each 32B sector) which is cheap.
    #pragma unroll
    for (int i = 0; i < 16; i++) {
        int f = t + i * 256;
        int node = f & 63;
        int kq   = f >> 6;          // 0..63 float4-chunks over k
        int gn = nodeBase + node;
        float4 v = make_float4(0.f, 0.f, 0.f, 0.f);
        if (gn < N_NODES) {
            if (kq < 32) {
                v = *(const float4*)(g_agg + (size_t)gn * D + kq * 4);
                float s = ssm[node];
                v.x *= s; v.y *= s; v.z *= s; v.w *= s;
            } else {
                v = *(const float4*)(x + (size_t)gn * D + (kq - 32) * 4);
            }
        }
        int k0 = kq * 4;
        tileT[(k0 + 0) * TN + node] = v.x;
        tileT[(k0 + 1) * TN + node] = v.y;
        tileT[(k0 + 2) * TN + node] = v.z;
        tileT[(k0 + 3) * TN + node] = v.w;
    }
    __syncthreads();

    const int c0 = (t & 31) * 4;      // 4 output cols per lane
    const int n0 = (t >> 5) * 8;      // 8 nodes per warp

    u64 acc[4][4];                    // [node-pair][col]
    #pragma unroll
    for (int p = 0; p < 4; p++)
        #pragma unroll
        for (int c = 0; c < 4; c++) acc[p][c] = 0ull;

    const float* aBase = tileT + n0;
    const float* wBase = Wsm + c0;

    #pragma unroll 4
    for (int k = 0; k < 256; k++) {
        // 8 nodes as 4 packed pairs: two 16B loads
        u64 a01, a23, a45, a67;
        asm("ld.shared.v2.b64 {%0, %1}, [%2];"
            : "=l"(a01), "=l"(a23) : "l"(aBase + k * TN));
        asm("ld.shared.v2.b64 {%0, %1}, [%2];"
            : "=l"(a45), "=l"(a67) : "l"(aBase + k * TN + 4));

        float4 w = *(const float4*)(wBase + k * WSTR);
        u64 wx, wy, wz, ww;
        asm("mov.b64 %0, {%1, %1};" : "=l"(wx) : "f"(w.x));
        asm("mov.b64 %0, {%1, %1};" : "=l"(wy) : "f"(w.y));
        asm("mov.b64 %0, {%1, %1};" : "=l"(wz) : "f"(w.z));
        asm("mov.b64 %0, {%1, %1};" : "=l"(ww) : "f"(w.w));

        ffma2(acc[0][0], a01, wx); ffma2(acc[0][1], a01, wy);
        ffma2(acc[0][2], a01, wz); ffma2(acc[0][3], a01, ww);
        ffma2(acc[1][0], a23, wx); ffma2(acc[1][1], a23, wy);
        ffma2(acc[1][2], a23, wz); ffma2(acc[1][3], a23, ww);
        ffma2(acc[2][0], a45, wx); ffma2(acc[2][1], a45, wy);
        ffma2(acc[2][2], a45, wz); ffma2(acc[2][3], a45, ww);
        ffma2(acc[3][0], a67, wx); ffma2(acc[3][1], a67, wy);
        ffma2(acc[3][2], a67, wz); ffma2(acc[3][3], a67, ww);
    }

    const float4 bias = *(const float4*)&b_l[c0];

    #pragma unroll
    for (int p = 0; p < 4; p++) {
        // unpack pair p -> nodes n0+2p (lo), n0+2p+1 (hi)
        float lo[4], hi[4];
        #pragma unroll
        for (int c = 0; c < 4; c++) {
            asm("mov.b64 {%0, %1}, %2;"
                : "=f"(lo[c]), "=f"(hi[c]) : "l"(acc[p][c]));
        }
        int nA = nodeBase + n0 + 2 * p;
        int nB = nA + 1;
        if (nA < N_NODES) {
            float4 o;
            o.x = fmaxf(lo[0] + bias.x, 0.f);
            o.y = fmaxf(lo[1] + bias.y, 0.f);
            o.z = fmaxf(lo[2] + bias.z, 0.f);
            o.w = fmaxf(lo[3] + bias.w, 0.f);
            *(float4*)&out[(size_t)nA * D + c0] = o;
        }
        if (nB < N_NODES) {
            float4 o;
            o.x = fmaxf(hi[0] + bias.x, 0.f);
            o.y = fmaxf(hi[1] + bias.y, 0.f);
            o.z = fmaxf(hi[2] + bias.z, 0.f);
            o.w = fmaxf(hi[3] + bias.w, 0.f);
            *(float4*)&out[(size_t)nB * D + c0] = o;
        }
    }
}

// ---------------------------------------------------------------------------
extern "C" void kernel_launch(void* const* d_in, const int* in_sizes, int n_in,
                              void* d_out, int out_size) {
    const float* x   = (const float*)d_in[0];
    const int*   ei  = (const int*)d_in[1];
    const float* W_l = (const float*)d_in[2];
    const float* b_l = (const float*)d_in[3];
    const float* W_r = (const float*)d_in[4];
    float*       out = (float*)d_out;

    cudaFuncSetAttribute(sage_gemm,
                         cudaFuncAttributeMaxDynamicSharedMemorySize,
                         SMEM_BYTES);

    zero_kernel<<<6250, 256>>>();
    scatter_kernel<<<100000, 256>>>(x, ei);
    sage_gemm<<<(N_NODES + TN - 1) / TN, 256, SMEM_BYTES>>>(x, W_l, b_l, W_r, out);
}

// round 9
// speedup vs baseline: 2.0437x; 1.0651x over previous
#include <cuda_runtime.h>
#include <cuda_bf16.h>

#define N_NODES 50000
#define N_EDGES 800000
#define D 128

typedef unsigned long long u64;

// ---------------------------------------------------------------------------
// Scratch (__device__ globals per allocation-free rule)
// ---------------------------------------------------------------------------
__device__ __align__(16) float g_agg[N_NODES * D];   // 25.6 MB
__device__ __align__(16) float g_deg[N_NODES];

// ---------------------------------------------------------------------------
// K1: zero accumulation scratch
// ---------------------------------------------------------------------------
__global__ void zero_kernel() {
    int i = blockIdx.x * blockDim.x + threadIdx.x;
    const int n4 = (N_NODES * D) / 4;
    if (i < n4) ((float4*)g_agg)[i] = make_float4(0.f, 0.f, 0.f, 0.f);
    if (i < N_NODES) g_deg[i] = 0.f;
}

// ---------------------------------------------------------------------------
// K3: edge scatter, FOUR edges per warp (MLP=4 row loads in flight).
// ---------------------------------------------------------------------------
__device__ __forceinline__ void red_add_v4(float* addr, float4 v) {
    asm volatile("red.global.add.v4.f32 [%0], {%1, %2, %3, %4};"
                 :: "l"(addr), "f"(v.x), "f"(v.y), "f"(v.z), "f"(v.w)
                 : "memory");
}

__global__ void __launch_bounds__(256) scatter_kernel(
    const float* __restrict__ x,
    const int* __restrict__ ei)
{
    unsigned tid = blockIdx.x * blockDim.x + threadIdx.x;
    unsigned w = tid >> 5;              // warp id = edge-quad id
    unsigned lane = tid & 31;
    unsigned base = w * 4;
    if (base >= N_EDGES) return;

    // broadcast loads of 4 src + 4 dst indices
    int4 s4 = *(const int4*)(ei + base);
    int4 d4 = *(const int4*)(ei + N_EDGES + base);

    bool ok0 = (unsigned)s4.x < N_NODES && (unsigned)d4.x < N_NODES;
    bool ok1 = (unsigned)s4.y < N_NODES && (unsigned)d4.y < N_NODES;
    bool ok2 = (unsigned)s4.z < N_NODES && (unsigned)d4.z < N_NODES;
    bool ok3 = (unsigned)s4.w < N_NODES && (unsigned)d4.w < N_NODES;

    const unsigned off = lane * 4;
    float4 v0, v1, v2, v3;
    // 4 independent row loads (deep MLP)
    if (ok0) v0 = *(const float4*)(x + (size_t)s4.x * D + off);
    if (ok1) v1 = *(const float4*)(x + (size_t)s4.y * D + off);
    if (ok2) v2 = *(const float4*)(x + (size_t)s4.z * D + off);
    if (ok3) v3 = *(const float4*)(x + (size_t)s4.w * D + off);

    if (ok0) red_add_v4(g_agg + (size_t)d4.x * D + off, v0);
    if (ok1) red_add_v4(g_agg + (size_t)d4.y * D + off, v1);
    if (ok2) red_add_v4(g_agg + (size_t)d4.z * D + off, v2);
    if (ok3) red_add_v4(g_agg + (size_t)d4.w * D + off, v3);

    if (lane == 0) {
        if (ok0) atomicAdd(&g_deg[d4.x], 1.0f);
        if (ok1) atomicAdd(&g_deg[d4.y], 1.0f);
        if (ok2) atomicAdd(&g_deg[d4.z], 1.0f);
        if (ok3) atomicAdd(&g_deg[d4.w], 1.0f);
    }
}

// ---------------------------------------------------------------------------
// K2/K4: half-GEMMs (K=128 each), ~100 KB smem -> 2 CTAs/SM.
//   PHASE 0 (before scatter):  out = x @ W_r^T + b          (pre-activation)
//   PHASE 1 (after scatter):   out = relu((agg/deg) @ W_l^T + out)
// PHASE 1 reads g_agg DIRECTLY in device code (a __device__ global's
// address must never be passed from host).
// ---------------------------------------------------------------------------
#define TN 64
#define WSTR 132
#define OFF_W 0                         // 128 x 132 floats
#define OFF_T (128 * WSTR)              // 16896: 128 k x 64 nodes
#define OFF_S (OFF_T + 128 * TN)        // 25088: inv-deg
#define H_SMEM_FLOATS (OFF_S + TN)
#define H_SMEM_BYTES  (H_SMEM_FLOATS * 4)   // 100,608 B

__device__ __forceinline__ void ffma2(u64& d, u64 a, u64 b) {
    asm("fma.rn.f32x2 %0, %1, %2, %0;" : "+l"(d) : "l"(a), "l"(b));
}

template <int PHASE>
__global__ void __launch_bounds__(256, 2) gemm_half(
    const float* __restrict__ x,       // used in PHASE 0 only
    const float* __restrict__ W,       // PHASE 0: W_r, PHASE 1: W_l
    const float* __restrict__ b_l,     // used in PHASE 0 only
    float* __restrict__ out)
{
    extern __shared__ float sm[];
    float* Wsm   = sm + OFF_W;
    float* tileT = sm + OFF_T;
    float* ssm   = sm + OFF_S;

    const int t = threadIdx.x;
    const int nodeBase = blockIdx.x * TN;

    // source matrix resolved in DEVICE code
    const float* src = (PHASE == 0) ? x : (const float*)g_agg;

    // Weights transposed: Wsm[k][c] = W[c][k]
    #pragma unroll 4
    for (int l = t; l < D * D; l += 256) {
        int c = l >> 7;
        int k = l & 127;
        Wsm[k * WSTR + c] = W[l];
    }

    if (PHASE == 1 && t < TN) {
        int n = nodeBase + t;
        float dg = (n < N_NODES) ? g_deg[n] : 1.0f;
        ssm[t] = 1.0f / fmaxf(dg, 1.0f);
    }
    __syncthreads();

    // Fill transposed tile: 64 nodes x 128 k = 2048 float4, 8 per thread.
    // Warp spans 32 consecutive nodes at fixed kq -> conflict-free STS.
    #pragma unroll
    for (int i = 0; i < 8; i++) {
        int f = t + i * 256;
        int node = f & 63;
        int kq   = f >> 6;              // 0..31
        int gn = nodeBase + node;
        float4 v = make_float4(0.f, 0.f, 0.f, 0.f);
        if (gn < N_NODES) {
            v = *(const float4*)(src + (size_t)gn * D + kq * 4);
            if (PHASE == 1) {
                float s = ssm[node];
                v.x *= s; v.y *= s; v.z *= s; v.w *= s;
            }
        }
        int k0 = kq * 4;
        tileT[(k0 + 0) * TN + node] = v.x;
        tileT[(k0 + 1) * TN + node] = v.y;
        tileT[(k0 + 2) * TN + node] = v.z;
        tileT[(k0 + 3) * TN + node] = v.w;
    }
    __syncthreads();

    const int c0 = (t & 31) * 4;        // 4 output cols per lane
    const int n0 = (t >> 5) * 8;        // 8 nodes per warp

    u64 acc[4][4];                      // [node-pair][col]
    #pragma unroll
    for (int p = 0; p < 4; p++)
        #pragma unroll
        for (int c = 0; c < 4; c++) acc[p][c] = 0ull;

    const float* aBase = tileT + n0;
    const float* wBase = Wsm + c0;

    #pragma unroll 4
    for (int k = 0; k < 128; k++) {
        u64 a01, a23, a45, a67;
        asm("ld.shared.v2.b64 {%0, %1}, [%2];"
            : "=l"(a01), "=l"(a23) : "l"(aBase + k * TN));
        asm("ld.shared.v2.b64 {%0, %1}, [%2];"
            : "=l"(a45), "=l"(a67) : "l"(aBase + k * TN + 4));

        float4 w = *(const float4*)(wBase + k * WSTR);
        u64 wx, wy, wz, ww;
        asm("mov.b64 %0, {%1, %1};" : "=l"(wx) : "f"(w.x));
        asm("mov.b64 %0, {%1, %1};" : "=l"(wy) : "f"(w.y));
        asm("mov.b64 %0, {%1, %1};" : "=l"(wz) : "f"(w.z));
        asm("mov.b64 %0, {%1, %1};" : "=l"(ww) : "f"(w.w));

        ffma2(acc[0][0], a01, wx); ffma2(acc[0][1], a01, wy);
        ffma2(acc[0][2], a01, wz); ffma2(acc[0][3], a01, ww);
        ffma2(acc[1][0], a23, wx); ffma2(acc[1][1], a23, wy);
        ffma2(acc[1][2], a23, wz); ffma2(acc[1][3], a23, ww);
        ffma2(acc[2][0], a45, wx); ffma2(acc[2][1], a45, wy);
        ffma2(acc[2][2], a45, wz); ffma2(acc[2][3], a45, ww);
        ffma2(acc[3][0], a67, wx); ffma2(acc[3][1], a67, wy);
        ffma2(acc[3][2], a67, wz); ffma2(acc[3][3], a67, ww);
    }

    float4 bias = make_float4(0.f, 0.f, 0.f, 0.f);
    if (PHASE == 0) bias = *(const float4*)&b_l[c0];

    #pragma unroll
    for (int p = 0; p < 4; p++) {
        float lo[4], hi[4];
        #pragma unroll
        for (int c = 0; c < 4; c++) {
            asm("mov.b64 {%0, %1}, %2;"
                : "=f"(lo[c]), "=f"(hi[c]) : "l"(acc[p][c]));
        }
        int nA = nodeBase + n0 + 2 * p;
        int nB = nA + 1;
        if (nA < N_NODES) {
            float4 o;
            if (PHASE == 0) {
                o.x = lo[0] + bias.x; o.y = lo[1] + bias.y;
                o.z = lo[2] + bias.z; o.w = lo[3] + bias.w;
            } else {
                float4 prev = *(const float4*)&out[(size_t)nA * D + c0];
                o.x = fmaxf(lo[0] + prev.x, 0.f);
                o.y = fmaxf(lo[1] + prev.y, 0.f);
                o.z = fmaxf(lo[2] + prev.z, 0.f);
                o.w = fmaxf(lo[3] + prev.w, 0.f);
            }
            *(float4*)&out[(size_t)nA * D + c0] = o;
        }
        if (nB < N_NODES) {
            float4 o;
            if (PHASE == 0) {
                o.x = hi[0] + bias.x; o.y = hi[1] + bias.y;
                o.z = hi[2] + bias.z; o.w = hi[3] + bias.w;
            } else {
                float4 prev = *(const float4*)&out[(size_t)nB * D + c0];
                o.x = fmaxf(hi[0] + prev.x, 0.f);
                o.y = fmaxf(hi[1] + prev.y, 0.f);
                o.z = fmaxf(hi[2] + prev.z, 0.f);
                o.w = fmaxf(hi[3] + prev.w, 0.f);
            }
            *(float4*)&out[(size_t)nB * D + c0] = o;
        }
    }
}

// ---------------------------------------------------------------------------
extern "C" void kernel_launch(void* const* d_in, const int* in_sizes, int n_in,
                              void* d_out, int out_size) {
    const float* x   = (const float*)d_in[0];
    const int*   ei  = (const int*)d_in[1];
    const float* W_l = (const float*)d_in[2];
    const float* b_l = (const float*)d_in[3];
    const float* W_r = (const float*)d_in[4];
    float*       out = (float*)d_out;

    cudaFuncSetAttribute(gemm_half<0>,
                         cudaFuncAttributeMaxDynamicSharedMemorySize, H_SMEM_BYTES);
    cudaFuncSetAttribute(gemm_half<1>,
                         cudaFuncAttributeMaxDynamicSharedMemorySize, H_SMEM_BYTES);

    const int gemm_grid = (N_NODES + TN - 1) / TN;   // 782

    zero_kernel<<<6250, 256>>>();
    // x-half GEMM does not depend on aggregation; run it before scatter
    gemm_half<0><<<gemm_grid, 256, H_SMEM_BYTES>>>(x, W_r, b_l, out);
    // 800000 edges / 4 per warp / 8 warps per block = 25000 blocks
    scatter_kernel<<<25000, 256>>>(x, ei);
    gemm_half<1><<<gemm_grid, 256, H_SMEM_BYTES>>>(x, W_l, b_l, out);
}